// round 15
// baseline (speedup 1.0000x reference)
#include <cuda_runtime.h>
#include <cuda_fp16.h>
#include <cstdint>

// ---------------- problem constants ----------------
#define KTOT 784            // 28*28 GEMM K
#define NHID 200            // hidden width
#define NPAD 208            // n-warp widths 56,56,56,40 (exact 200 + 8 pad rows)
#define NCLS 10
#define BM   64             // rows per CTA (2 CTAs/SM)
#define BK   64             // K per chunk
#define NCHUNK 13           // 12*64 + 16 (last chunk: 1 k-step)
#define ROWB 144            // bytes per fp16 row -> LDSM conflict-free
#define ACH  (BM * ROWB)    // 9216
#define BSTG (NPAD * ROWB)  // 29952 per B stage
#define BCPY (NHID * ROWB)  // 28800 actually copied
#define NTHREADS 256        // 8 warps = 2m x 4n

// ---------------- smem layout (bytes) ----------------
#define SM_FULL(s) ((s) * 8)                       // 0,8,16
#define SM_A(s)    (128 + (s) * ACH)               // 2 x 9216
#define SM_B(s)    (128 + 2 * ACH + (s) * BSTG)    // 3 x 29952
#define SMEM_TOTAL (128 + 2 * ACH + 3 * BSTG)      // 108416
// epilogue reuse (after final __syncthreads)
#define SM_HID     128                             // 64 x 210 floats
#define HSTRIDE    210
#define SM_W2E     (SM_HID + BM * HSTRIDE * 4)     // 53888
#define SM_OUTP    (SM_W2E + NHID * NCLS * 4)      // 61888

// Per-chunk images of W1eff^T (n-major rows, 144B stride) in fp16, 200 rows.
__device__ __align__(16) unsigned char g_wB[NCHUNK * BCPY];

// ---------------- PTX helpers ----------------
__device__ __forceinline__ uint32_t smem_u32(const void* p) {
    uint32_t a;
    asm("{ .reg .u64 t; cvta.to.shared.u64 t, %1; cvt.u32.u64 %0, t; }" : "=r"(a) : "l"(p));
    return a;
}

#define MBARRIER_INIT(a, n) \
    asm volatile("mbarrier.init.shared.b64 [%0], %1;" :: "r"(a), "r"((uint32_t)(n)) : "memory")
#define MBARRIER_EXPECT_TX(a, b) \
    asm volatile("mbarrier.arrive.expect_tx.shared.b64 _, [%0], %1;" :: "r"(a), "r"((uint32_t)(b)) : "memory")

#define MBARRIER_WAIT_PARITY(mbar, par) do {                                   \
    uint32_t _m = (mbar), _p = (par), _d;                                      \
    asm volatile("{\n\t.reg .pred p;\n\t"                                      \
        "mbarrier.try_wait.parity.acquire.cta.shared::cta.b64 p, [%1], %2;\n\t"\
        "selp.b32 %0, 1, 0, p;\n\t}"                                           \
        : "=r"(_d) : "r"(_m), "r"(_p) : "memory");                             \
    if (!_d) {                                                                 \
        asm volatile("{\n\t.reg .pred P1;\n\t"                                 \
            "W%=:\n\t"                                                         \
            "mbarrier.try_wait.parity.acquire.cta.shared::cta.b64 P1, [%0], %1, 0x989680;\n\t" \
            "@P1 bra.uni D%=;\n\t"                                             \
            "bra.uni W%=;\n\t"                                                 \
            "D%=:\n\t}" :: "r"(_m), "r"(_p) : "memory");                       \
    }                                                                          \
} while (0)

__device__ __forceinline__ void bulk_g2s(uint32_t dst, const void* src, uint32_t bytes, uint32_t mbar) {
    asm volatile("cp.async.bulk.shared::cta.global.mbarrier::complete_tx::bytes [%0], [%1], %2, [%3];"
        :: "r"(dst), "l"(src), "r"(bytes), "r"(mbar) : "memory");
}

__device__ __forceinline__ void ldsm4(uint32_t* d, uint32_t addr) {
    asm volatile("ldmatrix.sync.aligned.m8n8.x4.shared.b16 {%0,%1,%2,%3}, [%4];"
        : "=r"(d[0]), "=r"(d[1]), "=r"(d[2]), "=r"(d[3]) : "r"(addr));
}
__device__ __forceinline__ void ldsm2(uint32_t* d, uint32_t addr) {
    asm volatile("ldmatrix.sync.aligned.m8n8.x2.shared.b16 {%0,%1}, [%2];"
        : "=r"(d[0]), "=r"(d[1]) : "r"(addr));
}
__device__ __forceinline__ void mma16816(float* c, const uint32_t* a, const uint32_t* b) {
    asm volatile("mma.sync.aligned.m16n8k16.row.col.f32.f16.f16.f32 "
        "{%0,%1,%2,%3}, {%4,%5,%6,%7}, {%8,%9}, {%0,%1,%2,%3};"
        : "+f"(c[0]), "+f"(c[1]), "+f"(c[2]), "+f"(c[3])
        : "r"(a[0]), "r"(a[1]), "r"(a[2]), "r"(a[3]), "r"(b[0]), "r"(b[1]));
}

// ---------------------------------------------------------------------------
// Prep: W1eff[k][n], conv folded into w1; transposed [n][k] fp16 rows (144B),
// per-chunk images of exactly 200 rows.
// ---------------------------------------------------------------------------
__global__ void prep_kernel(const float* __restrict__ conv_w, const float* __restrict__ w1) {
    int p = blockIdx.x;    // k: 0..831
    int h = threadIdx.x;   // n: 0..199
    float s = 0.f;
    if (p < KTOT) {
        int y = p / 28, xx = p % 28;
#pragma unroll
        for (int di = 0; di < 3; ++di) {
            int oy = y - di;
            if (oy < 0 || oy > 25) continue;
#pragma unroll
            for (int dj = 0; dj < 3; ++dj) {
                int ox = xx - dj;
                if (ox < 0 || ox > 25) continue;
                s += conv_w[di * 3 + dj] * w1[(oy * 26 + ox) * NHID + h];
            }
        }
    }
    __half hv = __float2half_rn(s);
    int chunk = p >> 6, kl = p & 63;
    size_t off = (size_t)chunk * BCPY + (size_t)h * ROWB + (size_t)kl * 2;
    *(unsigned short*)(g_wB + off) = __half_as_ushort(hv);
}

// Convert 8 fp32 -> 8 fp16 (rn), packed pairs.
__device__ __forceinline__ void cvt8(float4 v0, float4 v1, uint4& hi) {
    __half2 h0 = __floats2half2_rn(v0.x, v0.y);
    __half2 h1 = __floats2half2_rn(v0.z, v0.w);
    __half2 h2 = __floats2half2_rn(v1.x, v1.y);
    __half2 h3 = __floats2half2_rn(v1.z, v1.w);
    hi.x = *reinterpret_cast<uint32_t*>(&h0);
    hi.y = *reinterpret_cast<uint32_t*>(&h1);
    hi.z = *reinterpret_cast<uint32_t*>(&h2);
    hi.w = *reinterpret_cast<uint32_t*>(&h3);
}

// One k16-step: NT4 full ldsm4 + 1 ldsm2 of B, 2 ldsm4 of A, (2*NT4+1)*2 MMAs.
template <int NT4>
__device__ __forceinline__ void kstep_t(uint32_t aB, uint32_t bB, uint32_t kb, float* acc) {
    uint32_t bf[NT4 * 4 + 2], ah[8];
#pragma unroll
    for (int tp = 0; tp < NT4; ++tp) ldsm4(&bf[tp * 4], bB + tp * (16 * ROWB) + kb);
    ldsm2(&bf[NT4 * 4], bB + NT4 * (16 * ROWB) + kb);
    ldsm4(&ah[0], aB + kb);
    ldsm4(&ah[4], aB + 16 * ROWB + kb);
#pragma unroll
    for (int mt = 0; mt < 2; ++mt)
#pragma unroll
        for (int tn = 0; tn < 2 * NT4 + 1; ++tn)
            mma16816(&acc[(mt * (2 * NT4 + 1) + tn) * 4], &ah[mt * 4], &bf[tn * 2]);
}

// ---------------------------------------------------------------------------
// Fused: out = relu(X @ W1eff + b1) @ w2 + b2  (plain fp16 mma.sync)
// BM=64, 2 CTAs/SM, 8 warps = 2m x 4n (tiles 32x56/56/56/40 = exact N=200).
// R11 chassis: per-chunk __syncthreads, A double-buffer, x reg-prefetch,
// warp-staggered k-steps. NEW: 3-stage B ring, prefetch distance 2.
// ---------------------------------------------------------------------------
__global__ __launch_bounds__(NTHREADS, 2)
void fused_mma_kernel(const float* __restrict__ x,
                      const float* __restrict__ b1,
                      const float* __restrict__ w2,
                      const float* __restrict__ b2,
                      float* __restrict__ out) {
    extern __shared__ __align__(1024) unsigned char smem[];
    const uint32_t sb = smem_u32(smem);
    const int tid  = threadIdx.x;
    const int wid  = tid >> 5;
    const int lane = tid & 31;
    const int m0   = blockIdx.x * BM;

    // this thread's two A-granules (m row, k-octet) within a chunk
    const int g_m0 = tid >> 3,           g_g0 = tid & 7;   // rows 0..31
    const int g_m1 = (tid + 256) >> 3;                     // rows 32..63

    if (tid == 0) {
#pragma unroll
        for (int s = 0; s < 3; ++s) MBARRIER_INIT(sb + SM_FULL(s), 1);
        // fill stages 0,1 (chunks 0,1)
        MBARRIER_EXPECT_TX(sb + SM_FULL(0), BCPY);
        bulk_g2s(sb + SM_B(0), g_wB, BCPY, sb + SM_FULL(0));
        MBARRIER_EXPECT_TX(sb + SM_FULL(1), BCPY);
        bulk_g2s(sb + SM_B(1), g_wB + BCPY, BCPY, sb + SM_FULL(1));
    }
    // zero B pad rows 200..207 of all 3 stages (1152B each; never copied)
    for (int e = tid; e < 3 * (NPAD - NHID) * ROWB / 4; e += NTHREADS) {
        int s = e / ((NPAD - NHID) * ROWB / 4);
        int w = e - s * ((NPAD - NHID) * ROWB / 4);
        *(uint32_t*)(smem + SM_B(s) + BCPY + w * 4) = 0;
    }
    // A(0): direct load + convert
    {
        const float4* s0 = (const float4*)(x + (size_t)(m0 + g_m0) * KTOT + g_g0 * 8);
        const float4* s1 = (const float4*)(x + (size_t)(m0 + g_m1) * KTOT + g_g0 * 8);
        uint4 h;
        cvt8(s0[0], s0[1], h);
        *(uint4*)(smem + SM_A(0) + g_m0 * ROWB + g_g0 * 16) = h;
        cvt8(s1[0], s1[1], h);
        *(uint4*)(smem + SM_A(0) + g_m1 * ROWB + g_g0 * 16) = h;
    }
    __syncthreads();   // mbarrier init + A(0) + pads visible

    const int lg = lane >> 3, lr = lane & 7;
    const uint32_t a_off = (uint32_t)(((lg & 1) * 8 + lr) * ROWB + (lg >> 1) * 16);
    const uint32_t b_off = (uint32_t)(((lg >> 1) * 8 + lr) * ROWB + (lg & 1) * 16);
    const int wm = (wid & 1) * 32;           // 2 m-warps
    const int wn = (wid >> 1) * 56;          // n base: 0,56,112,168
    const bool narrow = (wid >> 1) == 3;     // last n-warp: width 40
    const int ks0 = (wid & 1) * 2;           // stagger: odd m-warps start at kstep 2

    float acc[56];
#pragma unroll
    for (int i = 0; i < 56; ++i) acc[i] = 0.f;

    // ---------------- main loop ----------------
#pragma unroll 1
    for (int i = 0; i < NCHUNK; ++i) {
        const int s = i & 1;
        const bool hasNext = (i + 1 < NCHUNK);

        // issue B(i+2) into its ring stage (safe: stage consumed in chunk i-1,
        // all reads retired by the __syncthreads that ended chunk i-1)
        const int j = i + 2;
        if (j < NCHUNK && tid == 0) {
            const uint32_t mb = sb + SM_FULL(j % 3);
            MBARRIER_EXPECT_TX(mb, BCPY);
            bulk_g2s(sb + SM_B(j % 3), g_wB + (size_t)j * BCPY, BCPY, mb);
        }

        // issue global x loads for chunk i+1 (latency hidden behind MMAs)
        float4 p0a, p0b, p1a, p1b;
        bool val = false;
        if (hasNext) {
            const int kg = (i + 1) * BK + g_g0 * 8;
            val = kg < KTOT;
            if (val) {
                const float4* s0 = (const float4*)(x + (size_t)(m0 + g_m0) * KTOT + kg);
                const float4* s1 = (const float4*)(x + (size_t)(m0 + g_m1) * KTOT + kg);
                p0a = s0[0]; p0b = s0[1];
                p1a = s1[0]; p1b = s1[1];
            }
        }

        // wait for B(i) (prefetched 2 chunks ahead -> normally non-blocking)
        MBARRIER_WAIT_PARITY(sb + SM_FULL(i % 3), (i / 3) & 1);

        const uint32_t aB = sb + SM_A(s) + (uint32_t)wm * ROWB + a_off;
        const uint32_t bB = sb + SM_B(i % 3) + (uint32_t)wn * ROWB + b_off;

        if (i != NCHUNK - 1) {
            if (narrow) {
#pragma unroll
                for (int ks = 0; ks < 4; ++ks)
                    kstep_t<2>(aB, bB, (uint32_t)((((ks + ks0) & 3)) * 32), acc);
            } else {
#pragma unroll
                for (int ks = 0; ks < 4; ++ks)
                    kstep_t<3>(aB, bB, (uint32_t)((((ks + ks0) & 3)) * 32), acc);
            }
        } else {
            if (narrow) kstep_t<2>(aB, bB, 0, acc);   // 784 = 12*64 + 16
            else        kstep_t<3>(aB, bB, 0, acc);
        }

        // convert prefetched x(i+1) -> A(1-s) fp16
        if (hasNext) {
            uint4 h = {0, 0, 0, 0};
            if (val) cvt8(p0a, p0b, h);
            *(uint4*)(smem + SM_A(1 - s) + g_m0 * ROWB + g_g0 * 16) = h;
            uint4 h1 = {0, 0, 0, 0};
            if (val) cvt8(p1a, p1b, h1);
            *(uint4*)(smem + SM_A(1 - s) + g_m1 * ROWB + g_g0 * 16) = h1;
        }
        __syncthreads();
    }

    // ---------------- epilogue: relu(+b1) -> smem, then @ w2 + b2 ----------------
    float* hid  = (float*)(smem + SM_HID);    // [64][210]
    float* w2s  = (float*)(smem + SM_W2E);    // [200][10]
    float* outp = (float*)(smem + SM_OUTP);   // [64][10]

    {
        const int ntn = narrow ? 5 : 7;
#pragma unroll
        for (int mt = 0; mt < 2; ++mt) {
            for (int tn = 0; tn < 7; ++tn) {
                if (tn >= ntn) break;
                int c = wn + tn * 8 + (lane & 3) * 2;
                if (c < NHID) {
                    int r0 = wm + mt * 16 + (lane >> 2);
                    float b1a = b1[c], b1b = b1[c + 1];
                    const float* a = &acc[(mt * ntn + tn) * 4];
                    hid[r0 * HSTRIDE + c]           = fmaxf(a[0] + b1a, 0.f);
                    hid[r0 * HSTRIDE + c + 1]       = fmaxf(a[1] + b1b, 0.f);
                    hid[(r0 + 8) * HSTRIDE + c]     = fmaxf(a[2] + b1a, 0.f);
                    hid[(r0 + 8) * HSTRIDE + c + 1] = fmaxf(a[3] + b1b, 0.f);
                }
            }
        }
    }
    for (int e = tid; e < NHID * NCLS; e += NTHREADS) w2s[e] = w2[e];
    for (int e = tid; e < BM * NCLS; e += NTHREADS)  outp[e] = 0.f;
    __syncthreads();

    {
        int m  = tid >> 2;                  // 0..63
        int h0 = (tid & 3) * 50;            // 4 k-slices of 50
        float p[NCLS];
#pragma unroll
        for (int c = 0; c < NCLS; ++c) p[c] = 0.f;
        for (int h = h0; h < h0 + 50; ++h) {
            float v = hid[m * HSTRIDE + h];
#pragma unroll
            for (int c = 0; c < NCLS; ++c) p[c] += v * w2s[h * NCLS + c];
        }
#pragma unroll
        for (int c = 0; c < NCLS; ++c) atomicAdd(&outp[m * NCLS + c], p[c]);
    }
    __syncthreads();

    for (int e = tid; e < BM * NCLS; e += NTHREADS)
        out[(size_t)m0 * NCLS + e] = outp[e] + b2[e % NCLS];
}

// ---------------------------------------------------------------------------
extern "C" void kernel_launch(void* const* d_in, const int* in_sizes, int n_in,
                              void* d_out, int out_size) {
    const float* x      = (const float*)d_in[0];   // [65536, 784]
    const float* conv_w = (const float*)d_in[1];   // [3, 3]
    const float* w1     = (const float*)d_in[2];   // [676, 200]
    const float* b1     = (const float*)d_in[3];   // [200]
    const float* w2     = (const float*)d_in[4];   // [200, 10]
    const float* b2     = (const float*)d_in[5];   // [10]
    float* out          = (float*)d_out;           // [65536, 10]

    cudaFuncSetAttribute(fused_mma_kernel,
                         cudaFuncAttributeMaxDynamicSharedMemorySize, SMEM_TOTAL);

    prep_kernel<<<NCHUNK * BK, NHID>>>(conv_w, w1);
    fused_mma_kernel<<<65536 / BM, NTHREADS, SMEM_TOTAL>>>(x, b1, w2, b2, out);
}

// round 16
// speedup vs baseline: 1.0427x; 1.0427x over previous
#include <cuda_runtime.h>
#include <cuda_fp16.h>
#include <cstdint>

// ---------------- problem constants ----------------
#define KTOT 784            // 28*28 GEMM K
#define NHID 200            // hidden width
#define NPAD 208            // n-warp widths 56,56,56,40 (exact 200 + 8 pad rows)
#define NCLS 10
#define BM   64             // rows per CTA (2 CTAs/SM)
#define BK   64             // K per chunk
#define NCHUNK 13           // 12*64 + 16 (last chunk: 1 k-step)
#define ROWB 144            // bytes per fp16 row -> LDSM conflict-free
#define ACH  (BM * ROWB)    // 9216
#define BRES (NPAD * ROWB)  // 29952 per B stage
#define BCPY (NHID * ROWB)  // 28800 actually copied
#define NTHREADS 256        // 8 warps = 2m x 4n

// ---------------- smem layout (bytes) ----------------
#define SM_MB0   0
#define SM_MB1   8
#define SM_W2    64                         // 2000 floats
#define SM_B1    8064                       // 200 floats
#define SM_B2    8864                       // 10 floats
#define SM_ABASE 9216
#define SM_A(s)  (SM_ABASE + (s) * ACH)                        // 2 x 9216
#define SM_BBASE (SM_ABASE + 2 * ACH)                          // 27648
#define SM_B(s)  (SM_BBASE + (s) * BRES)                       // 2 x 29952
#define SMEM_TOTAL (SM_BBASE + 2 * BRES)                       // 87552
// epilogue reuse
#define SM_HID   9216                       // 64 x 210 floats
#define HSTRIDE  210
#define SM_OUTP  (SM_HID + BM * HSTRIDE * 4)                   // 62976

// Per-chunk images of W1eff^T (n-major rows, 144B stride) in fp16, 200 rows.
__device__ __align__(16) unsigned char g_wB[NCHUNK * BCPY];

// ---------------- PTX helpers ----------------
__device__ __forceinline__ uint32_t smem_u32(const void* p) {
    uint32_t a;
    asm("{ .reg .u64 t; cvta.to.shared.u64 t, %1; cvt.u32.u64 %0, t; }" : "=r"(a) : "l"(p));
    return a;
}

#define MBARRIER_INIT(a, n) \
    asm volatile("mbarrier.init.shared.b64 [%0], %1;" :: "r"(a), "r"((uint32_t)(n)) : "memory")
#define MBARRIER_EXPECT_TX(a, b) \
    asm volatile("mbarrier.arrive.expect_tx.shared.b64 _, [%0], %1;" :: "r"(a), "r"((uint32_t)(b)) : "memory")

#define MBARRIER_WAIT_PARITY(mbar, par) do {                                   \
    uint32_t _m = (mbar), _p = (par), _d;                                      \
    asm volatile("{\n\t.reg .pred p;\n\t"                                      \
        "mbarrier.try_wait.parity.acquire.cta.shared::cta.b64 p, [%1], %2;\n\t"\
        "selp.b32 %0, 1, 0, p;\n\t}"                                           \
        : "=r"(_d) : "r"(_m), "r"(_p) : "memory");                             \
    if (!_d) {                                                                 \
        asm volatile("{\n\t.reg .pred P1;\n\t"                                 \
            "W%=:\n\t"                                                         \
            "mbarrier.try_wait.parity.acquire.cta.shared::cta.b64 P1, [%0], %1, 0x989680;\n\t" \
            "@P1 bra.uni D%=;\n\t"                                             \
            "bra.uni W%=;\n\t"                                                 \
            "D%=:\n\t}" :: "r"(_m), "r"(_p) : "memory");                       \
    }                                                                          \
} while (0)

__device__ __forceinline__ void bulk_g2s(uint32_t dst, const void* src, uint32_t bytes, uint32_t mbar) {
    asm volatile("cp.async.bulk.shared::cta.global.mbarrier::complete_tx::bytes [%0], [%1], %2, [%3];"
        :: "r"(dst), "l"(src), "r"(bytes), "r"(mbar) : "memory");
}

__device__ __forceinline__ void ldsm4(uint32_t* d, uint32_t addr) {
    asm volatile("ldmatrix.sync.aligned.m8n8.x4.shared.b16 {%0,%1,%2,%3}, [%4];"
        : "=r"(d[0]), "=r"(d[1]), "=r"(d[2]), "=r"(d[3]) : "r"(addr));
}
__device__ __forceinline__ void ldsm2(uint32_t* d, uint32_t addr) {
    asm volatile("ldmatrix.sync.aligned.m8n8.x2.shared.b16 {%0,%1}, [%2];"
        : "=r"(d[0]), "=r"(d[1]) : "r"(addr));
}
__device__ __forceinline__ void mma16816(float* c, const uint32_t* a, const uint32_t* b) {
    asm volatile("mma.sync.aligned.m16n8k16.row.col.f32.f16.f16.f32 "
        "{%0,%1,%2,%3}, {%4,%5,%6,%7}, {%8,%9}, {%0,%1,%2,%3};"
        : "+f"(c[0]), "+f"(c[1]), "+f"(c[2]), "+f"(c[3])
        : "r"(a[0]), "r"(a[1]), "r"(a[2]), "r"(a[3]), "r"(b[0]), "r"(b[1]));
}

// ---------------------------------------------------------------------------
// Prep: W1eff[k][n], conv folded into w1; transposed [n][k] fp16 rows (144B),
// per-chunk images of exactly 200 rows.
// ---------------------------------------------------------------------------
__global__ void prep_kernel(const float* __restrict__ conv_w, const float* __restrict__ w1) {
    int p = blockIdx.x;    // k: 0..831
    int h = threadIdx.x;   // n: 0..199
    float s = 0.f;
    if (p < KTOT) {
        int y = p / 28, xx = p % 28;
#pragma unroll
        for (int di = 0; di < 3; ++di) {
            int oy = y - di;
            if (oy < 0 || oy > 25) continue;
#pragma unroll
            for (int dj = 0; dj < 3; ++dj) {
                int ox = xx - dj;
                if (ox < 0 || ox > 25) continue;
                s += conv_w[di * 3 + dj] * w1[(oy * 26 + ox) * NHID + h];
            }
        }
    }
    __half hv = __float2half_rn(s);
    int chunk = p >> 6, kl = p & 63;
    size_t off = (size_t)chunk * BCPY + (size_t)h * ROWB + (size_t)kl * 2;
    *(unsigned short*)(g_wB + off) = __half_as_ushort(hv);
}

// Convert 8 fp32 -> 8 fp16 (rn), packed pairs.
__device__ __forceinline__ void cvt8(float4 v0, float4 v1, uint4& hi) {
    __half2 h0 = __floats2half2_rn(v0.x, v0.y);
    __half2 h1 = __floats2half2_rn(v0.z, v0.w);
    __half2 h2 = __floats2half2_rn(v1.x, v1.y);
    __half2 h3 = __floats2half2_rn(v1.z, v1.w);
    hi.x = *reinterpret_cast<uint32_t*>(&h0);
    hi.y = *reinterpret_cast<uint32_t*>(&h1);
    hi.z = *reinterpret_cast<uint32_t*>(&h2);
    hi.w = *reinterpret_cast<uint32_t*>(&h3);
}

// One k16-step: NT4 full ldsm4 + 1 ldsm2 of B, 2 ldsm4 of A, (2*NT4+1)*2 MMAs.
// NT4=3 -> 7 n-tiles (56 cols, as R11); NT4=2 -> 5 n-tiles (40 cols).
template <int NT4>
__device__ __forceinline__ void kstep_t(uint32_t aB, uint32_t bB, uint32_t kb, float* acc) {
    uint32_t bf[NT4 * 4 + 2], ah[8];
#pragma unroll
    for (int tp = 0; tp < NT4; ++tp) ldsm4(&bf[tp * 4], bB + tp * (16 * ROWB) + kb);
    ldsm2(&bf[NT4 * 4], bB + NT4 * (16 * ROWB) + kb);
    ldsm4(&ah[0], aB + kb);
    ldsm4(&ah[4], aB + 16 * ROWB + kb);
#pragma unroll
    for (int mt = 0; mt < 2; ++mt)
#pragma unroll
        for (int tn = 0; tn < 2 * NT4 + 1; ++tn)
            mma16816(&acc[(mt * (2 * NT4 + 1) + tn) * 4], &ah[mt * 4], &bf[tn * 2]);
}

// ---------------------------------------------------------------------------
// Fused: out = relu(X @ W1eff + b1) @ w2 + b2  (plain fp16 mma.sync)
// EXACT R11 chassis (2-stage B double-buffer, per-chunk sync, x reg-prefetch,
// warp-staggered k-steps); only change: N padded to 208, last n-warp width 40.
// ---------------------------------------------------------------------------
__global__ __launch_bounds__(NTHREADS, 2)
void fused_mma_kernel(const float* __restrict__ x,
                      const float* __restrict__ b1,
                      const float* __restrict__ w2,
                      const float* __restrict__ b2,
                      float* __restrict__ out) {
    extern __shared__ __align__(1024) unsigned char smem[];
    const uint32_t sb = smem_u32(smem);
    const int tid  = threadIdx.x;
    const int wid  = tid >> 5;
    const int lane = tid & 31;
    const int m0   = blockIdx.x * BM;

    // this thread's two A-granules (m row, k-octet) within a chunk
    const int g_m0 = tid >> 3,           g_g0 = tid & 7;   // rows 0..31
    const int g_m1 = (tid + 256) >> 3;                     // rows 32..63

    float* w2s = (float*)(smem + SM_W2);
    float* b1s = (float*)(smem + SM_B1);
    float* b2s = (float*)(smem + SM_B2);

    if (tid == 0) {
        MBARRIER_INIT(sb + SM_MB0, 1);
        MBARRIER_INIT(sb + SM_MB1, 1);
    }
    for (int e = tid; e < NHID * NCLS; e += NTHREADS) w2s[e] = w2[e];
    for (int e = tid; e < NHID; e += NTHREADS)        b1s[e] = b1[e];
    if (tid < NCLS)                                   b2s[tid] = b2[tid];
    // zero B pad rows 200..207 of both stages (never copied; must not be NaN)
    for (int e = tid; e < 2 * (NPAD - NHID) * ROWB / 4; e += NTHREADS) {
        int s = e >= (NPAD - NHID) * ROWB / 4;
        int w = e - s * ((NPAD - NHID) * ROWB / 4);
        *(uint32_t*)(smem + SM_B(s) + BCPY + w * 4) = 0;
    }
    __syncthreads();

    const int lg = lane >> 3, lr = lane & 7;
    const uint32_t a_off = (uint32_t)(((lg & 1) * 8 + lr) * ROWB + (lg >> 1) * 16);
    const uint32_t b_off = (uint32_t)(((lg >> 1) * 8 + lr) * ROWB + (lg & 1) * 16);
    const int wm = (wid & 1) * 32;           // 2 m-warps
    const int wn = (wid >> 1) * 56;          // n base: 0,56,112,168
    const bool narrow = (wid >> 1) == 3;     // last n-warp: width 40
    const int ks0 = (wid & 1) * 2;           // stagger: odd m-warps start at kstep 2

    float acc[56];
#pragma unroll
    for (int i = 0; i < 56; ++i) acc[i] = 0.f;

    // ---------------- prologue: B(0) bulk, A(0) direct load + convert ----------------
    if (tid == 0) {
        MBARRIER_EXPECT_TX(sb + SM_MB0, BCPY);
        bulk_g2s(sb + SM_B(0), g_wB, BCPY, sb + SM_MB0);
    }
    {
        const float4* s0 = (const float4*)(x + (size_t)(m0 + g_m0) * KTOT + g_g0 * 8);
        const float4* s1 = (const float4*)(x + (size_t)(m0 + g_m1) * KTOT + g_g0 * 8);
        uint4 h;
        cvt8(s0[0], s0[1], h);
        *(uint4*)(smem + SM_A(0) + g_m0 * ROWB + g_g0 * 16) = h;
        cvt8(s1[0], s1[1], h);
        *(uint4*)(smem + SM_A(0) + g_m1 * ROWB + g_g0 * 16) = h;
    }
    __syncthreads();

    // ---------------- main loop ----------------
#pragma unroll 1
    for (int i = 0; i < NCHUNK; ++i) {
        const int s = i & 1;
        const bool hasNext = (i + 1 < NCHUNK);

        // issue B(i+1) bulk into the other buffer (freed by last sync)
        if (hasNext && tid == 0) {
            const uint32_t mb = sb + (s ? SM_MB0 : SM_MB1);
            MBARRIER_EXPECT_TX(mb, BCPY);
            bulk_g2s(sb + SM_B(1 - s), g_wB + (size_t)(i + 1) * BCPY, BCPY, mb);
        }

        // issue global x loads for chunk i+1 (latency hidden behind MMAs)
        float4 p0a, p0b, p1a, p1b;
        bool val = false;
        if (hasNext) {
            const int kg = (i + 1) * BK + g_g0 * 8;
            val = kg < KTOT;
            if (val) {
                const float4* s0 = (const float4*)(x + (size_t)(m0 + g_m0) * KTOT + kg);
                const float4* s1 = (const float4*)(x + (size_t)(m0 + g_m1) * KTOT + kg);
                p0a = s0[0]; p0b = s0[1];
                p1a = s1[0]; p1b = s1[1];
            }
        }

        // wait for B(i)
        MBARRIER_WAIT_PARITY(sb + (s ? SM_MB1 : SM_MB0), (i >> 1) & 1);

        const uint32_t aB = sb + SM_A(s) + (uint32_t)wm * ROWB + a_off;
        const uint32_t bB = sb + SM_B(s) + (uint32_t)wn * ROWB + b_off;

        if (i != NCHUNK - 1) {
            if (narrow) {
                kstep_t<2>(aB, bB, (uint32_t)(((0 + ks0) & 3) * 32), acc);
                kstep_t<2>(aB, bB, (uint32_t)(((1 + ks0) & 3) * 32), acc);
                kstep_t<2>(aB, bB, (uint32_t)(((2 + ks0) & 3) * 32), acc);
                kstep_t<2>(aB, bB, (uint32_t)(((3 + ks0) & 3) * 32), acc);
            } else {
                kstep_t<3>(aB, bB, (uint32_t)(((0 + ks0) & 3) * 32), acc);
                kstep_t<3>(aB, bB, (uint32_t)(((1 + ks0) & 3) * 32), acc);
                kstep_t<3>(aB, bB, (uint32_t)(((2 + ks0) & 3) * 32), acc);
                kstep_t<3>(aB, bB, (uint32_t)(((3 + ks0) & 3) * 32), acc);
            }
        } else {
            if (narrow) kstep_t<2>(aB, bB, 0, acc);   // 784 = 12*64 + 16
            else        kstep_t<3>(aB, bB, 0, acc);
        }

        // convert prefetched x(i+1) -> A(1-s) fp16
        if (hasNext) {
            uint4 h = {0, 0, 0, 0};
            if (val) cvt8(p0a, p0b, h);
            *(uint4*)(smem + SM_A(1 - s) + g_m0 * ROWB + g_g0 * 16) = h;
            uint4 h1 = {0, 0, 0, 0};
            if (val) cvt8(p1a, p1b, h1);
            *(uint4*)(smem + SM_A(1 - s) + g_m1 * ROWB + g_g0 * 16) = h1;
        }
        __syncthreads();
    }

    // ---------------- epilogue: relu(+b1) -> smem, then @ w2 + b2 ----------------
    float* hid  = (float*)(smem + SM_HID);    // [64][210]
    float* outp = (float*)(smem + SM_OUTP);   // [64][10]

    {
        const int ntn = narrow ? 5 : 7;
#pragma unroll
        for (int mt = 0; mt < 2; ++mt) {
            for (int tn = 0; tn < 7; ++tn) {
                if (tn >= ntn) break;
                int c = wn + tn * 8 + (lane & 3) * 2;
                if (c < NHID) {
                    int r0 = wm + mt * 16 + (lane >> 2);
                    float b1a = b1s[c], b1b = b1s[c + 1];
                    const float* a = &acc[(mt * ntn + tn) * 4];
                    hid[r0 * HSTRIDE + c]           = fmaxf(a[0] + b1a, 0.f);
                    hid[r0 * HSTRIDE + c + 1]       = fmaxf(a[1] + b1b, 0.f);
                    hid[(r0 + 8) * HSTRIDE + c]     = fmaxf(a[2] + b1a, 0.f);
                    hid[(r0 + 8) * HSTRIDE + c + 1] = fmaxf(a[3] + b1b, 0.f);
                }
            }
        }
    }
    for (int e = tid; e < BM * NCLS; e += NTHREADS) outp[e] = 0.f;
    __syncthreads();

    {
        int m  = tid >> 2;                  // 0..63
        int h0 = (tid & 3) * 50;            // 4 k-slices of 50
        float p[NCLS];
#pragma unroll
        for (int c = 0; c < NCLS; ++c) p[c] = 0.f;
        for (int h = h0; h < h0 + 50; ++h) {
            float v = hid[m * HSTRIDE + h];
#pragma unroll
            for (int c = 0; c < NCLS; ++c) p[c] += v * w2s[h * NCLS + c];
        }
#pragma unroll
        for (int c = 0; c < NCLS; ++c) atomicAdd(&outp[m * NCLS + c], p[c]);
    }
    __syncthreads();

    for (int e = tid; e < BM * NCLS; e += NTHREADS)
        out[(size_t)m0 * NCLS + e] = outp[e] + b2s[e % NCLS];
}

// ---------------------------------------------------------------------------
extern "C" void kernel_launch(void* const* d_in, const int* in_sizes, int n_in,
                              void* d_out, int out_size) {
    const float* x      = (const float*)d_in[0];   // [65536, 784]
    const float* conv_w = (const float*)d_in[1];   // [3, 3]
    const float* w1     = (const float*)d_in[2];   // [676, 200]
    const float* b1     = (const float*)d_in[3];   // [200]
    const float* w2     = (const float*)d_in[4];   // [200, 10]
    const float* b2     = (const float*)d_in[5];   // [10]
    float* out          = (float*)d_out;           // [65536, 10]

    cudaFuncSetAttribute(fused_mma_kernel,
                         cudaFuncAttributeMaxDynamicSharedMemorySize, SMEM_TOTAL);

    prep_kernel<<<NCHUNK * BK, NHID>>>(conv_w, w1);
    fused_mma_kernel<<<65536 / BM, NTHREADS, SMEM_TOTAL>>>(x, b1, w2, b2, out);
}

// round 17
// speedup vs baseline: 1.7681x; 1.6957x over previous
#include <cuda_runtime.h>
#include <cuda_fp16.h>
#include <cstdint>

// ---------------- problem constants ----------------
#define KTOT 784            // 28*28 GEMM K
#define NHID 200            // hidden width (exact: 5 n-warps x 40)
#define NCLS 10
#define BM   64             // rows per CTA (2 CTAs/SM)
#define BK   64             // K per chunk
#define NCHUNK 13           // 12*64 + 16 (last chunk: 1 k-step)
#define ROWB 144            // bytes per fp16 row -> LDSM conflict-free
#define ACH  (BM * ROWB)    // 9216
#define BCPY (NHID * ROWB)  // 28800 per B stage (exact, no pad)
#define NTHREADS 320        // 10 warps = 2m x 5n, tile 32x40

// ---------------- smem layout (bytes) ----------------
#define SM_MB0   0
#define SM_MB1   8
#define SM_W2    64                         // 2000 floats
#define SM_B1    8064                       // 200 floats
#define SM_B2    8864                       // 10 floats
#define SM_ABASE 9216
#define SM_A(s)  (SM_ABASE + (s) * ACH)                        // 2 x 9216
#define SM_BBASE (SM_ABASE + 2 * ACH)                          // 27648
#define SM_B(s)  (SM_BBASE + (s) * BCPY)                       // 2 x 28800
#define SMEM_TOTAL (SM_BBASE + 2 * BCPY)                       // 85248
// epilogue reuse
#define SM_HID   9216                       // 64 x 210 floats
#define HSTRIDE  210
#define SM_OUTP  (SM_HID + BM * HSTRIDE * 4)                   // 62976

// Per-chunk images of W1eff^T (n-major rows, 144B stride) in fp16, 200 rows.
__device__ __align__(16) unsigned char g_wB[NCHUNK * BCPY];

// ---------------- PTX helpers ----------------
__device__ __forceinline__ uint32_t smem_u32(const void* p) {
    uint32_t a;
    asm("{ .reg .u64 t; cvta.to.shared.u64 t, %1; cvt.u32.u64 %0, t; }" : "=r"(a) : "l"(p));
    return a;
}

#define MBARRIER_INIT(a, n) \
    asm volatile("mbarrier.init.shared.b64 [%0], %1;" :: "r"(a), "r"((uint32_t)(n)) : "memory")
#define MBARRIER_EXPECT_TX(a, b) \
    asm volatile("mbarrier.arrive.expect_tx.shared.b64 _, [%0], %1;" :: "r"(a), "r"((uint32_t)(b)) : "memory")

#define MBARRIER_WAIT_PARITY(mbar, par) do {                                   \
    uint32_t _m = (mbar), _p = (par), _d;                                      \
    asm volatile("{\n\t.reg .pred p;\n\t"                                      \
        "mbarrier.try_wait.parity.acquire.cta.shared::cta.b64 p, [%1], %2;\n\t"\
        "selp.b32 %0, 1, 0, p;\n\t}"                                           \
        : "=r"(_d) : "r"(_m), "r"(_p) : "memory");                             \
    if (!_d) {                                                                 \
        asm volatile("{\n\t.reg .pred P1;\n\t"                                 \
            "W%=:\n\t"                                                         \
            "mbarrier.try_wait.parity.acquire.cta.shared::cta.b64 P1, [%0], %1, 0x989680;\n\t" \
            "@P1 bra.uni D%=;\n\t"                                             \
            "bra.uni W%=;\n\t"                                                 \
            "D%=:\n\t}" :: "r"(_m), "r"(_p) : "memory");                       \
    }                                                                          \
} while (0)

__device__ __forceinline__ void bulk_g2s(uint32_t dst, const void* src, uint32_t bytes, uint32_t mbar) {
    asm volatile("cp.async.bulk.shared::cta.global.mbarrier::complete_tx::bytes [%0], [%1], %2, [%3];"
        :: "r"(dst), "l"(src), "r"(bytes), "r"(mbar) : "memory");
}

__device__ __forceinline__ void ldsm4(uint32_t* d, uint32_t addr) {
    asm volatile("ldmatrix.sync.aligned.m8n8.x4.shared.b16 {%0,%1,%2,%3}, [%4];"
        : "=r"(d[0]), "=r"(d[1]), "=r"(d[2]), "=r"(d[3]) : "r"(addr));
}
__device__ __forceinline__ void ldsm2(uint32_t* d, uint32_t addr) {
    asm volatile("ldmatrix.sync.aligned.m8n8.x2.shared.b16 {%0,%1}, [%2];"
        : "=r"(d[0]), "=r"(d[1]) : "r"(addr));
}
__device__ __forceinline__ void mma16816(float* c, const uint32_t* a, const uint32_t* b) {
    asm volatile("mma.sync.aligned.m16n8k16.row.col.f32.f16.f16.f32 "
        "{%0,%1,%2,%3}, {%4,%5,%6,%7}, {%8,%9}, {%0,%1,%2,%3};"
        : "+f"(c[0]), "+f"(c[1]), "+f"(c[2]), "+f"(c[3])
        : "r"(a[0]), "r"(a[1]), "r"(a[2]), "r"(a[3]), "r"(b[0]), "r"(b[1]));
}

// ---------------------------------------------------------------------------
// Prep: W1eff[k][n], conv folded into w1; transposed [n][k] fp16 rows (144B),
// per-chunk images of exactly 200 rows.
// ---------------------------------------------------------------------------
__global__ void prep_kernel(const float* __restrict__ conv_w, const float* __restrict__ w1) {
    int p = blockIdx.x;    // k: 0..831
    int h = threadIdx.x;   // n: 0..199
    float s = 0.f;
    if (p < KTOT) {
        int y = p / 28, xx = p % 28;
#pragma unroll
        for (int di = 0; di < 3; ++di) {
            int oy = y - di;
            if (oy < 0 || oy > 25) continue;
#pragma unroll
            for (int dj = 0; dj < 3; ++dj) {
                int ox = xx - dj;
                if (ox < 0 || ox > 25) continue;
                s += conv_w[di * 3 + dj] * w1[(oy * 26 + ox) * NHID + h];
            }
        }
    }
    __half hv = __float2half_rn(s);
    int chunk = p >> 6, kl = p & 63;
    size_t off = (size_t)chunk * BCPY + (size_t)h * ROWB + (size_t)kl * 2;
    *(unsigned short*)(g_wB + off) = __half_as_ushort(hv);
}

// Convert 8 fp32 -> 8 fp16 (rn), packed pairs.
__device__ __forceinline__ void cvt8(float4 v0, float4 v1, uint4& hi) {
    __half2 h0 = __floats2half2_rn(v0.x, v0.y);
    __half2 h1 = __floats2half2_rn(v0.z, v0.w);
    __half2 h2 = __floats2half2_rn(v1.x, v1.y);
    __half2 h3 = __floats2half2_rn(v1.z, v1.w);
    hi.x = *reinterpret_cast<uint32_t*>(&h0);
    hi.y = *reinterpret_cast<uint32_t*>(&h1);
    hi.z = *reinterpret_cast<uint32_t*>(&h2);
    hi.w = *reinterpret_cast<uint32_t*>(&h3);
}

// One k16-step of the 32x40 warp tile: 5 n-tiles, 10 MMAs, 3 B-ldsm, 2 A-ldsm.
__device__ __forceinline__ void kstep(uint32_t aB, uint32_t bB, uint32_t kb, float* acc) {
    uint32_t bf[10], ah[8];
    ldsm4(&bf[0], bB + 0 * (16 * ROWB) + kb);
    ldsm4(&bf[4], bB + 1 * (16 * ROWB) + kb);
    ldsm2(&bf[8], bB + 2 * (16 * ROWB) + kb);
    ldsm4(&ah[0], aB + kb);
    ldsm4(&ah[4], aB + 16 * ROWB + kb);
#pragma unroll
    for (int mt = 0; mt < 2; ++mt)
#pragma unroll
        for (int tn = 0; tn < 5; ++tn)
            mma16816(&acc[(mt * 5 + tn) * 4], &ah[mt * 4], &bf[tn * 2]);
}

// ---------------------------------------------------------------------------
// Fused: out = relu(X @ W1eff + b1) @ w2 + b2  (plain fp16 mma.sync)
// BM=64, 2 CTAs/SM, 10 warps = 2m x 5n, UNIFORM tile 32x40 (exact N=200).
// R11 chassis: 2-stage B double-buffer, per-chunk __syncthreads, x reg-
// prefetch, warp-staggered k-steps. 20 warps/SM resident.
// ---------------------------------------------------------------------------
__global__ __launch_bounds__(NTHREADS, 2)
void fused_mma_kernel(const float* __restrict__ x,
                      const float* __restrict__ b1,
                      const float* __restrict__ w2,
                      const float* __restrict__ b2,
                      float* __restrict__ out) {
    extern __shared__ __align__(1024) unsigned char smem[];
    const uint32_t sb = smem_u32(smem);
    const int tid  = threadIdx.x;
    const int wid  = tid >> 5;
    const int lane = tid & 31;
    const int m0   = blockIdx.x * BM;

    // A-convert granules: 512 total (64 rows x 8 octets); thread owns
    // granule tid and (if tid<192) granule tid+320. 320%8==0 -> same octet.
    const int g_m0 = tid >> 3, g_g0 = tid & 7;     // rows 0..39
    const int g_m1 = g_m0 + 40;                    // rows 40..63 (tid<192)
    const bool has2 = tid < 192;

    float* w2s = (float*)(smem + SM_W2);
    float* b1s = (float*)(smem + SM_B1);
    float* b2s = (float*)(smem + SM_B2);

    if (tid == 0) {
        MBARRIER_INIT(sb + SM_MB0, 1);
        MBARRIER_INIT(sb + SM_MB1, 1);
    }
    for (int e = tid; e < NHID * NCLS; e += NTHREADS) w2s[e] = w2[e];
    for (int e = tid; e < NHID; e += NTHREADS)        b1s[e] = b1[e];
    if (tid < NCLS)                                   b2s[tid] = b2[tid];
    __syncthreads();

    const int lg = lane >> 3, lr = lane & 7;
    const uint32_t a_off = (uint32_t)(((lg & 1) * 8 + lr) * ROWB + (lg >> 1) * 16);
    const uint32_t b_off = (uint32_t)(((lg >> 1) * 8 + lr) * ROWB + (lg & 1) * 16);
    const int wm = (wid & 1) * 32;           // 2 m-warps
    const int wn = (wid >> 1) * 40;          // 5 n-warps: 0,40,80,120,160
    const int ks0 = (wid & 1) * 2;           // stagger: odd m-warps start at kstep 2

    float acc[40];
#pragma unroll
    for (int i = 0; i < 40; ++i) acc[i] = 0.f;

    // ---------------- prologue: B(0) bulk, A(0) direct load + convert ----------------
    if (tid == 0) {
        MBARRIER_EXPECT_TX(sb + SM_MB0, BCPY);
        bulk_g2s(sb + SM_B(0), g_wB, BCPY, sb + SM_MB0);
    }
    {
        const float4* s0 = (const float4*)(x + (size_t)(m0 + g_m0) * KTOT + g_g0 * 8);
        uint4 h;
        cvt8(s0[0], s0[1], h);
        *(uint4*)(smem + SM_A(0) + g_m0 * ROWB + g_g0 * 16) = h;
        if (has2) {
            const float4* s1 = (const float4*)(x + (size_t)(m0 + g_m1) * KTOT + g_g0 * 8);
            cvt8(s1[0], s1[1], h);
            *(uint4*)(smem + SM_A(0) + g_m1 * ROWB + g_g0 * 16) = h;
        }
    }
    __syncthreads();

    // ---------------- main loop ----------------
#pragma unroll 1
    for (int i = 0; i < NCHUNK; ++i) {
        const int s = i & 1;
        const bool hasNext = (i + 1 < NCHUNK);

        // issue B(i+1) bulk into the other buffer (freed by last sync)
        if (hasNext && tid == 0) {
            const uint32_t mb = sb + (s ? SM_MB0 : SM_MB1);
            MBARRIER_EXPECT_TX(mb, BCPY);
            bulk_g2s(sb + SM_B(1 - s), g_wB + (size_t)(i + 1) * BCPY, BCPY, mb);
        }

        // issue global x loads for chunk i+1 (latency hidden behind MMAs)
        float4 p0a, p0b, p1a, p1b;
        bool val = false;
        if (hasNext) {
            const int kg = (i + 1) * BK + g_g0 * 8;
            val = kg < KTOT;
            if (val) {
                const float4* s0 = (const float4*)(x + (size_t)(m0 + g_m0) * KTOT + kg);
                p0a = s0[0]; p0b = s0[1];
                if (has2) {
                    const float4* s1 = (const float4*)(x + (size_t)(m0 + g_m1) * KTOT + kg);
                    p1a = s1[0]; p1b = s1[1];
                }
            }
        }

        // wait for B(i)
        MBARRIER_WAIT_PARITY(sb + (s ? SM_MB1 : SM_MB0), (i >> 1) & 1);

        const uint32_t aB = sb + SM_A(s) + (uint32_t)wm * ROWB + a_off;
        const uint32_t bB = sb + SM_B(s) + (uint32_t)wn * ROWB + b_off;

        if (i != NCHUNK - 1) {
            kstep(aB, bB, (uint32_t)(((0 + ks0) & 3) * 32), acc);
            kstep(aB, bB, (uint32_t)(((1 + ks0) & 3) * 32), acc);
            kstep(aB, bB, (uint32_t)(((2 + ks0) & 3) * 32), acc);
            kstep(aB, bB, (uint32_t)(((3 + ks0) & 3) * 32), acc);
        } else {
            kstep(aB, bB, 0, acc);   // 784 = 12*64 + 16
        }

        // convert prefetched x(i+1) -> A(1-s) fp16
        if (hasNext) {
            uint4 h = {0, 0, 0, 0};
            if (val) cvt8(p0a, p0b, h);
            *(uint4*)(smem + SM_A(1 - s) + g_m0 * ROWB + g_g0 * 16) = h;
            if (has2) {
                uint4 h1 = {0, 0, 0, 0};
                if (val) cvt8(p1a, p1b, h1);
                *(uint4*)(smem + SM_A(1 - s) + g_m1 * ROWB + g_g0 * 16) = h1;
            }
        }
        __syncthreads();
    }

    // ---------------- epilogue: relu(+b1) -> smem, then @ w2 + b2 ----------------
    float* hid  = (float*)(smem + SM_HID);    // [64][210]
    float* outp = (float*)(smem + SM_OUTP);   // [64][10]

#pragma unroll
    for (int mt = 0; mt < 2; ++mt) {
#pragma unroll
        for (int tn = 0; tn < 5; ++tn) {
            int c = wn + tn * 8 + (lane & 3) * 2;
            int r0 = wm + mt * 16 + (lane >> 2);
            float b1a = b1s[c], b1b = b1s[c + 1];
            const float* a = &acc[(mt * 5 + tn) * 4];
            hid[r0 * HSTRIDE + c]           = fmaxf(a[0] + b1a, 0.f);
            hid[r0 * HSTRIDE + c + 1]       = fmaxf(a[1] + b1b, 0.f);
            hid[(r0 + 8) * HSTRIDE + c]     = fmaxf(a[2] + b1a, 0.f);
            hid[(r0 + 8) * HSTRIDE + c + 1] = fmaxf(a[3] + b1b, 0.f);
        }
    }
    for (int e = tid; e < BM * NCLS; e += NTHREADS) outp[e] = 0.f;
    __syncthreads();

    {
        int m  = tid & 63;                  // 0..63
        int h0 = (tid >> 6) * 40;           // 5 k-slices of 40
        float p[NCLS];
#pragma unroll
        for (int c = 0; c < NCLS; ++c) p[c] = 0.f;
        for (int h = h0; h < h0 + 40; ++h) {
            float v = hid[m * HSTRIDE + h];
#pragma unroll
            for (int c = 0; c < NCLS; ++c) p[c] += v * w2s[h * NCLS + c];
        }
#pragma unroll
        for (int c = 0; c < NCLS; ++c) atomicAdd(&outp[m * NCLS + c], p[c]);
    }
    __syncthreads();

    for (int e = tid; e < BM * NCLS; e += NTHREADS)
        out[(size_t)m0 * NCLS + e] = outp[e] + b2s[e % NCLS];
}

// ---------------------------------------------------------------------------
extern "C" void kernel_launch(void* const* d_in, const int* in_sizes, int n_in,
                              void* d_out, int out_size) {
    const float* x      = (const float*)d_in[0];   // [65536, 784]
    const float* conv_w = (const float*)d_in[1];   // [3, 3]
    const float* w1     = (const float*)d_in[2];   // [676, 200]
    const float* b1     = (const float*)d_in[3];   // [200]
    const float* w2     = (const float*)d_in[4];   // [200, 10]
    const float* b2     = (const float*)d_in[5];   // [10]
    float* out          = (float*)d_out;           // [65536, 10]

    cudaFuncSetAttribute(fused_mma_kernel,
                         cudaFuncAttributeMaxDynamicSharedMemorySize, SMEM_TOTAL);

    prep_kernel<<<NCHUNK * BK, NHID>>>(conv_w, w1);
    fused_mma_kernel<<<65536 / BM, NTHREADS, SMEM_TOTAL>>>(x, b1, w2, b2, out);
}